// round 15
// baseline (speedup 1.0000x reference)
#include <cuda_runtime.h>
#include <cuda_bf16.h>
#include <cuda_fp8.h>
#include <cstdint>
#include <math.h>

#define NB   8
#define NC   256
#define NH   128
#define NW   128
#define NHW  (NH * NW)        // 16384

// ---------------------------------------------------------------------------
// Scratch (device globals: allocation-guard safe; 16B-aligned for vector ops)
// ---------------------------------------------------------------------------
__device__ __align__(16) __nv_bfloat16 g_x_hi[(size_t)NB * NC * NHW];   // [b][c][n]
__device__ __align__(16) __nv_bfloat16 g_x_lo[(size_t)NB * NC * NHW];
__device__ __align__(16) uint8_t g_x8[(size_t)NB * NHW * 512];          // [b][n][k']
__device__ __align__(16) __nv_bfloat16 g_qkv_hi[(size_t)NB * 3 * NC * NHW];
__device__ __align__(16) __nv_bfloat16 g_qkv_lo[(size_t)NB * 3 * NC * NHW];
__device__ __align__(16) __nv_bfloat16 g_att_hi[(size_t)NB * NC * NHW];
__device__ __align__(16) __nv_bfloat16 g_att_lo[(size_t)NB * NC * NHW];
__device__ __align__(16) __nv_bfloat16 g_w_hi[4 * NC * NC];             // [o][c]
__device__ __align__(16) __nv_bfloat16 g_w_lo[4 * NC * NC];
__device__ __align__(16) __nv_bfloat16 g_wv_his[NC * NC];               // bf16(wv_hi)*512
__device__ __align__(16) uint8_t g_w8frag[16 * 16 * 32 * 16];           // V fp8 A-frags
__device__ __align__(16) float g_bias[4 * NC];

// ---------------------------------------------------------------------------
// PTX helpers
// ---------------------------------------------------------------------------
__device__ __forceinline__ uint32_t smem_u32(const void* p) {
  uint32_t a;
  asm("{ .reg .u64 t; cvta.to.shared.u64 t, %1; cvt.u32.u64 %0, t; }"
      : "=r"(a) : "l"(p));
  return a;
}
__device__ __forceinline__ void cp_async16(uint32_t sdst, const void* gsrc) {
  asm volatile("cp.async.cg.shared.global [%0], [%1], 16;"
               :: "r"(sdst), "l"(gsrc));
}
#define CP_COMMIT() asm volatile("cp.async.commit_group;" ::: "memory")
#define CP_WAIT0()  asm volatile("cp.async.wait_group 0;" ::: "memory")
#define CP_WAIT1()  asm volatile("cp.async.wait_group 1;" ::: "memory")

__device__ __forceinline__ void ldsm_x4(uint32_t* r, uint32_t addr) {
  asm volatile("ldmatrix.sync.aligned.m8n8.x4.shared.b16 {%0,%1,%2,%3}, [%4];"
               : "=r"(r[0]), "=r"(r[1]), "=r"(r[2]), "=r"(r[3]) : "r"(addr));
}
__device__ __forceinline__ void ldsm_x4_t(uint32_t* r, uint32_t addr) {
  asm volatile("ldmatrix.sync.aligned.m8n8.x4.trans.shared.b16 {%0,%1,%2,%3}, [%4];"
               : "=r"(r[0]), "=r"(r[1]), "=r"(r[2]), "=r"(r[3]) : "r"(addr));
}
__device__ __forceinline__ void mma_bf16(float* d, const uint32_t* a,
                                         uint32_t b0, uint32_t b1) {
  asm volatile(
      "mma.sync.aligned.m16n8k16.row.col.f32.bf16.bf16.f32 "
      "{%0,%1,%2,%3}, {%4,%5,%6,%7}, {%8,%9}, {%0,%1,%2,%3};"
      : "+f"(d[0]), "+f"(d[1]), "+f"(d[2]), "+f"(d[3])
      : "r"(a[0]), "r"(a[1]), "r"(a[2]), "r"(a[3]), "r"(b0), "r"(b1));
}
__device__ __forceinline__ void mma_fp8(float* d, const uint32_t* a,
                                        uint32_t b0, uint32_t b1) {
  asm volatile(
      "mma.sync.aligned.m16n8k32.row.col.f32.e4m3.e4m3.f32 "
      "{%0,%1,%2,%3}, {%4,%5,%6,%7}, {%8,%9}, {%0,%1,%2,%3};"
      : "+f"(d[0]), "+f"(d[1]), "+f"(d[2]), "+f"(d[3])
      : "r"(a[0]), "r"(a[1]), "r"(a[2]), "r"(a[3]), "r"(b0), "r"(b1));
}
__device__ __forceinline__ float ex2(float x) {
  float r;
  asm("ex2.approx.f32 %0, %1;" : "=f"(r) : "f"(x));
  return r;
}
__device__ __forceinline__ uint32_t pack_hi(float a, float b) {
  __nv_bfloat162 p = {__float2bfloat16(a), __float2bfloat16(b)};
  return *(uint32_t*)&p;
}
__device__ __forceinline__ uint32_t pack_lo(float a, float b) {
  __nv_bfloat16 ha = __float2bfloat16(a), hb = __float2bfloat16(b);
  __nv_bfloat162 p = {__float2bfloat16(a - __bfloat162float(ha)),
                      __float2bfloat16(b - __bfloat162float(hb))};
  return *(uint32_t*)&p;
}
__device__ __forceinline__ uint8_t f8(float v) {
  return (uint8_t)__nv_cvt_float_to_fp8(v, __NV_SATFINITE, __NV_E4M3);
}

// ---------------------------------------------------------------------------
// Transposing converter: x fp32 [c][n] -> bf16 hi/lo [c][n] + fp8 [n][k']
// k' < 256: fp8(xl*512) at k'=c;  k' >= 256: fp8(xh) at k'=256+c.
// smem tile stride 68 floats (272 B): float4-aligned for every row.
// ---------------------------------------------------------------------------
__global__ __launch_bounds__(256) void split_t(
    const float* __restrict__ X,
    __nv_bfloat16* __restrict__ H, __nv_bfloat16* __restrict__ L,
    uint8_t* __restrict__ X8) {
  __shared__ float t[32][68];
  const int b  = blockIdx.y;
  const int n0 = blockIdx.x * 64;
  const int tid = threadIdx.x;
  const int r  = tid >> 3, sg = tid & 7;     // load coords
  const int nn = tid >> 2, cs = tid & 3;     // transpose coords

  for (int cc = 0; cc < 8; cc++) {
    const int c = cc * 32 + r;
    const size_t off = ((size_t)b * NC + c) * NHW + n0 + sg * 8;
    float4 v0 = *(const float4*)(X + off);
    float4 v1 = *(const float4*)(X + off + 4);
    *(uint4*)(H + off) = make_uint4(pack_hi(v0.x, v0.y), pack_hi(v0.z, v0.w),
                                    pack_hi(v1.x, v1.y), pack_hi(v1.z, v1.w));
    *(uint4*)(L + off) = make_uint4(pack_lo(v0.x, v0.y), pack_lo(v0.z, v0.w),
                                    pack_lo(v1.x, v1.y), pack_lo(v1.z, v1.w));
    *(float4*)(&t[r][sg * 8])     = v0;
    *(float4*)(&t[r][sg * 8 + 4]) = v1;
    __syncthreads();

    uint32_t lw0 = 0, lw1 = 0, hw0 = 0, hw1 = 0;
#pragma unroll
    for (int j = 0; j < 4; j++) {
      float v = t[cs * 8 + j][nn];
      float hf = __bfloat162float(__float2bfloat16(v));
      hw0 |= (uint32_t)f8(hf) << (8 * j);
      lw0 |= (uint32_t)f8((v - hf) * 512.0f) << (8 * j);
      float v2 = t[cs * 8 + 4 + j][nn];
      float hf2 = __bfloat162float(__float2bfloat16(v2));
      hw1 |= (uint32_t)f8(hf2) << (8 * j);
      lw1 |= (uint32_t)f8((v2 - hf2) * 512.0f) << (8 * j);
    }
    uint8_t* dst = X8 + ((size_t)b * NHW + n0 + nn) * 512 + cc * 32 + cs * 8;
    *(uint2*)(dst)       = make_uint2(lw0, lw1);   // fp8(xl*512)
    *(uint2*)(dst + 256) = make_uint2(hw0, hw1);   // fp8(xh)
    __syncthreads();
  }
}

// ---------------------------------------------------------------------------
// Weight converter: bf16 hi/lo for all 4; V extras: scaled-hi bf16 + fp8 frags
// ---------------------------------------------------------------------------
__global__ __launch_bounds__(256) void convert_w(
    const float* __restrict__ w0, const float* __restrict__ w1,
    const float* __restrict__ w2, const float* __restrict__ w3,
    const float* __restrict__ b0, const float* __restrict__ b1,
    const float* __restrict__ b2, const float* __restrict__ b3,
    __nv_bfloat16* __restrict__ H, __nv_bfloat16* __restrict__ L) {
  const float* ws[4] = {w0, w1, w2, w3};
  const float* bs[4] = {b0, b1, b2, b3};
  int m = blockIdx.y;
  int i = blockIdx.x * 256 + threadIdx.x;
  float v = ws[m][i];
  __nv_bfloat16 h = __float2bfloat16(v);
  float hf = __bfloat162float(h);
  H[m * NC * NC + i] = h;
  L[m * NC * NC + i] = __float2bfloat16(v - hf);
  if (blockIdx.x == 0) g_bias[m * NC + threadIdx.x] = bs[m][threadIdx.x];

  if (m == 2) {   // V weight extras
    int o = i >> 8, c = i & 255;
    g_wv_his[i] = __float2bfloat16(hf * 512.0f);
    float lf = v - hf;
    // fp8 m16n8k32 A-fragment byte position for element (o, k')
    auto fragoff = [](int o, int kp) {
      int s = kp >> 5, w = kp & 31;
      int half = (w >> 4) & 1, tt = (w >> 2) & 3, byt = w & 3;
      int gg = o & 7, up = (o >> 3) & 1, r16 = o >> 4;
      int reg = up + 2 * half;
      return (((r16 * 16 + s) * 32) + (gg * 4 + tt)) * 16 + reg * 4 + byt;
    };
    g_w8frag[fragoff(o, c)]       = f8(hf);            // pairs fp8(xl*512)
    g_w8frag[fragoff(o, c + 256)] = f8(lf * 512.0f);   // pairs fp8(xh)
  }
}

// ---------------------------------------------------------------------------
// mma.sync bf16-split GEMM (best measured, unchanged) — QK + out-proj
// ---------------------------------------------------------------------------
#define OFF_AH   0
#define OFF_AL   10240
#define OFF_BH   20480
#define OFF_BL   29184
#define BUF_BYTES 37888
#define SMEM_GEMM (3 * BUF_BYTES)

__global__ __launch_bounds__(256, 2) void gemm_mma(
    const __nv_bfloat16* __restrict__ Xh, const __nv_bfloat16* __restrict__ Xl,
    const __nv_bfloat16* __restrict__ Wh, const __nv_bfloat16* __restrict__ Wl,
    const float* __restrict__ bias, float* __restrict__ Yf,
    __nv_bfloat16* __restrict__ Yh, __nv_bfloat16* __restrict__ Yl,
    int ocnt) {
  extern __shared__ __align__(16) char sm[];
  const uint32_t smb = smem_u32(sm);

  const int tid  = threadIdx.x;
  const int lane = tid & 31;
  const int wid  = tid >> 5;
  const int wm   = wid & 3;
  const int wn   = wid >> 2;
  const int b    = blockIdx.z;
  const int o0   = blockIdx.x * 128;
  const int n0   = blockIdx.y * 128;

  const __nv_bfloat16* Xbh = Xh + (size_t)b * NC * NHW + n0;
  const __nv_bfloat16* Xbl = Xl + (size_t)b * NC * NHW + n0;
  const __nv_bfloat16* Wbh = Wh + (size_t)o0 * NC;
  const __nv_bfloat16* Wbl = Wl + (size_t)o0 * NC;

  const int a_row0 = tid >> 2, a_seg = tid & 3;
  const int b_row0 = tid >> 4, b_seg = tid & 15;

  float acc[2][8][4];
#pragma unroll
  for (int mt = 0; mt < 2; mt++)
#pragma unroll
    for (int nt = 0; nt < 8; nt++)
#pragma unroll
      for (int e = 0; e < 4; e++) acc[mt][nt][e] = 0.f;

  const int lr = lane & 15, lc = lane >> 4;
  uint32_t a_base = (uint32_t)((wm * 32 + lr) * 80 + lc * 16);
  uint32_t b_base = (uint32_t)(lr * 272 + wn * 128 + lc * 16);

  auto stage = [&](int it, int slot) {
    const int c0 = it * 32;
    const uint32_t sb = smb + slot * BUF_BYTES;
#pragma unroll
    for (int r = 0; r < 2; r++) {
      int row = a_row0 + r * 64;
      uint32_t so = (uint32_t)(row * 80 + a_seg * 16);
      cp_async16(sb + OFF_AH + so, Wbh + (size_t)row * NC + c0 + a_seg * 8);
      cp_async16(sb + OFF_AL + so, Wbl + (size_t)row * NC + c0 + a_seg * 8);
    }
#pragma unroll
    for (int r = 0; r < 2; r++) {
      int row = b_row0 + r * 16;
      uint32_t so = (uint32_t)(row * 272 + b_seg * 16);
      cp_async16(sb + OFF_BH + so, Xbh + (size_t)(c0 + row) * NHW + b_seg * 8);
      cp_async16(sb + OFF_BL + so, Xbl + (size_t)(c0 + row) * NHW + b_seg * 8);
    }
    CP_COMMIT();
  };

  stage(0, 0);
  stage(1, 1);

  int slot = 0;
  for (int it = 0; it < 8; it++) {
    if (it < 7) { CP_WAIT1(); } else { CP_WAIT0(); }
    __syncthreads();
    int pslot = slot + 2 >= 3 ? slot - 1 : slot + 2;
    if (it + 2 < 8) stage(it + 2, pslot);

    const uint32_t sb = smb + slot * BUF_BYTES;
#pragma unroll
    for (int ks = 0; ks < 2; ks++) {
      uint32_t ah[2][4], al[2][4];
#pragma unroll
      for (int mt = 0; mt < 2; mt++) {
        uint32_t ao = sb + a_base + (uint32_t)(mt * 16 * 80 + ks * 32);
        ldsm_x4(ah[mt], ao + OFF_AH);
        ldsm_x4(al[mt], ao + OFF_AL);
      }
#pragma unroll
      for (int nt2 = 0; nt2 < 4; nt2++) {
        uint32_t bh[4], bl[4];
        uint32_t bo = sb + b_base + (uint32_t)(ks * 16 * 272 + nt2 * 32);
        ldsm_x4_t(bh, bo + OFF_BH);
        ldsm_x4_t(bl, bo + OFF_BL);
        mma_bf16(acc[0][nt2 * 2],     ah[0], bh[0], bh[1]);
        mma_bf16(acc[0][nt2 * 2 + 1], ah[0], bh[2], bh[3]);
        mma_bf16(acc[1][nt2 * 2],     ah[1], bh[0], bh[1]);
        mma_bf16(acc[1][nt2 * 2 + 1], ah[1], bh[2], bh[3]);
        mma_bf16(acc[0][nt2 * 2],     ah[0], bl[0], bl[1]);
        mma_bf16(acc[0][nt2 * 2 + 1], ah[0], bl[2], bl[3]);
        mma_bf16(acc[1][nt2 * 2],     ah[1], bl[0], bl[1]);
        mma_bf16(acc[1][nt2 * 2 + 1], ah[1], bl[2], bl[3]);
        mma_bf16(acc[0][nt2 * 2],     al[0], bh[0], bh[1]);
        mma_bf16(acc[0][nt2 * 2 + 1], al[0], bh[2], bh[3]);
        mma_bf16(acc[1][nt2 * 2],     al[1], bh[0], bh[1]);
        mma_bf16(acc[1][nt2 * 2 + 1], al[1], bh[2], bh[3]);
      }
    }
    slot = slot + 1 >= 3 ? 0 : slot + 1;
  }
  __syncthreads();

#pragma unroll
  for (int mt = 0; mt < 2; mt++) {
    int o = o0 + wm * 32 + mt * 16 + (lane >> 2);
    float bv0 = __ldg(bias + o);
    float bv1 = __ldg(bias + o + 8);
#pragma unroll
    for (int nt = 0; nt < 8; nt++) {
      int n = n0 + wn * 64 + nt * 8 + (lane & 3) * 2;
      float v00 = acc[mt][nt][0] + bv0, v01 = acc[mt][nt][1] + bv0;
      float v10 = acc[mt][nt][2] + bv1, v11 = acc[mt][nt][3] + bv1;
      size_t off0 = ((size_t)b * ocnt + o) * NHW + n;
      size_t off1 = ((size_t)b * ocnt + o + 8) * NHW + n;
      if (Yf) {
        *(float2*)(Yf + off0) = make_float2(v00, v01);
        *(float2*)(Yf + off1) = make_float2(v10, v11);
      } else {
        *(uint32_t*)(Yh + off0) = pack_hi(v00, v01);
        *(uint32_t*)(Yh + off1) = pack_hi(v10, v11);
        *(uint32_t*)(Yl + off0) = pack_lo(v00, v01);
        *(uint32_t*)(Yl + off1) = pack_lo(v10, v11);
      }
    }
  }
}

// ---------------------------------------------------------------------------
// V-projection GEMM: main bf16 (W*512) + ONE fp8 pass for both corrections.
// All terms share one accumulator at 512x scale; epilogue * 1/512.
// ---------------------------------------------------------------------------
#define V_OFF_A  0
#define V_OFF_B  10240
#define V_BUF    18944
#define SMEM_VGEMM (3 * V_BUF)

__global__ __launch_bounds__(256, 2) void vgemm_mma(
    const __nv_bfloat16* __restrict__ Xh, const uint8_t* __restrict__ X8,
    const __nv_bfloat16* __restrict__ Whs, const uint8_t* __restrict__ W8,
    const float* __restrict__ bias,
    __nv_bfloat16* __restrict__ Yh, __nv_bfloat16* __restrict__ Yl) {
  extern __shared__ __align__(16) char sm[];
  const uint32_t smb = smem_u32(sm);

  const int tid  = threadIdx.x;
  const int lane = tid & 31;
  const int wid  = tid >> 5;
  const int wm   = wid & 3;
  const int wn   = wid >> 2;
  const int b    = blockIdx.z;
  const int o0   = blockIdx.x * 128;
  const int n0   = blockIdx.y * 128;

  const __nv_bfloat16* Xbh = Xh + (size_t)b * NC * NHW + n0;
  const __nv_bfloat16* Wb  = Whs + (size_t)o0 * NC;
  const uint8_t* X8b = X8 + (size_t)b * NHW * 512;

  const int a_row0 = tid >> 2, a_seg = tid & 3;
  const int b_row0 = tid >> 4, b_seg = tid & 15;

  float acc[2][8][4];
#pragma unroll
  for (int mt = 0; mt < 2; mt++)
#pragma unroll
    for (int nt = 0; nt < 8; nt++)
#pragma unroll
      for (int e = 0; e < 4; e++) acc[mt][nt][e] = 0.f;

  const int lr = lane & 15, lc = lane >> 4;
  const int g = lane >> 2, tig = lane & 3;
  uint32_t a_base = (uint32_t)((wm * 32 + lr) * 80 + lc * 16);
  uint32_t b_base = (uint32_t)(lr * 272 + wn * 128 + lc * 16);
  const int r16b = (o0 >> 4) + wm * 2;

  auto stage = [&](int it, int slot) {
    const int c0 = it * 32;
    const uint32_t sb = smb + slot * V_BUF;
#pragma unroll
    for (int r = 0; r < 2; r++) {
      int row = a_row0 + r * 64;
      cp_async16(sb + V_OFF_A + (uint32_t)(row * 80 + a_seg * 16),
                 Wb + (size_t)row * NC + c0 + a_seg * 8);
    }
#pragma unroll
    for (int r = 0; r < 2; r++) {
      int row = b_row0 + r * 16;
      cp_async16(sb + V_OFF_B + (uint32_t)(row * 272 + b_seg * 16),
                 Xbh + (size_t)(c0 + row) * NHW + b_seg * 8);
    }
    CP_COMMIT();
  };

  stage(0, 0);
  stage(1, 1);

  int slot = 0;
  for (int it = 0; it < 8; it++) {
    if (it < 7) { CP_WAIT1(); } else { CP_WAIT0(); }
    __syncthreads();
    int pslot = slot + 2 >= 3 ? slot - 1 : slot + 2;
    if (it + 2 < 8) stage(it + 2, pslot);

    const uint32_t sb = smb + slot * V_BUF;
#pragma unroll
    for (int ks = 0; ks < 2; ks++) {
      const int s = it * 2 + ks;     // fp8 k'-slab 0..15
      uint4 af0 = *(const uint4*)(W8 + (size_t)(((r16b + 0) * 16 + s) * 32 + lane) * 16);
      uint4 af1 = *(const uint4*)(W8 + (size_t)(((r16b + 1) * 16 + s) * 32 + lane) * 16);
      uint32_t b0v[8], b1v[8];
#pragma unroll
      for (int nt = 0; nt < 8; nt++) {
        const uint8_t* bp = X8b + (size_t)(n0 + wn * 64 + nt * 8 + g) * 512 + s * 32 + 4 * tig;
        b0v[nt] = *(const uint32_t*)bp;
        b1v[nt] = *(const uint32_t*)(bp + 16);
      }

      // main bf16 (hi*hi at 512x scale)
      uint32_t ah[2][4];
#pragma unroll
      for (int mt = 0; mt < 2; mt++)
        ldsm_x4(ah[mt], sb + V_OFF_A + a_base + (uint32_t)(mt * 16 * 80 + ks * 32));
#pragma unroll
      for (int nt2 = 0; nt2 < 4; nt2++) {
        uint32_t bh[4];
        ldsm_x4_t(bh, sb + V_OFF_B + b_base + (uint32_t)(ks * 16 * 272 + nt2 * 32));
        mma_bf16(acc[0][nt2 * 2],     ah[0], bh[0], bh[1]);
        mma_bf16(acc[0][nt2 * 2 + 1], ah[0], bh[2], bh[3]);
        mma_bf16(acc[1][nt2 * 2],     ah[1], bh[0], bh[1]);
        mma_bf16(acc[1][nt2 * 2 + 1], ah[1], bh[2], bh[3]);
      }

      // fp8 corrections (both split terms in one k32 pass)
#pragma unroll
      for (int nt = 0; nt < 8; nt++) {
        mma_fp8(acc[0][nt], (const uint32_t*)&af0, b0v[nt], b1v[nt]);
        mma_fp8(acc[1][nt], (const uint32_t*)&af1, b0v[nt], b1v[nt]);
      }
    }
    slot = slot + 1 >= 3 ? 0 : slot + 1;
  }
  __syncthreads();

  const float INV = 1.0f / 512.0f;
#pragma unroll
  for (int mt = 0; mt < 2; mt++) {
    int o = o0 + wm * 32 + mt * 16 + g;
    float bv0 = __ldg(bias + o);
    float bv1 = __ldg(bias + o + 8);
#pragma unroll
    for (int nt = 0; nt < 8; nt++) {
      int n = n0 + wn * 64 + nt * 8 + tig * 2;
      float v00 = acc[mt][nt][0] * INV + bv0, v01 = acc[mt][nt][1] * INV + bv0;
      float v10 = acc[mt][nt][2] * INV + bv1, v11 = acc[mt][nt][3] * INV + bv1;
      size_t off0 = ((size_t)b * (3 * NC) + 512 + o) * NHW + n;
      size_t off1 = off0 + (size_t)8 * NHW;
      *(uint32_t*)(Yh + off0) = pack_hi(v00, v01);
      *(uint32_t*)(Yh + off1) = pack_hi(v10, v11);
      *(uint32_t*)(Yl + off0) = pack_lo(v00, v01);
      *(uint32_t*)(Yl + off1) = pack_lo(v10, v11);
    }
  }
}

// ---------------------------------------------------------------------------
// Persistent tensor-core attention (R11 best — unchanged)
// ---------------------------------------------------------------------------
#define AT_Q 0
#define AT_K 69632
#define AT_V 139264
#define SMEM_ATTN 208896

__global__ __launch_bounds__(256) void attn_mma(
    const __nv_bfloat16* __restrict__ QKVh,
    const __nv_bfloat16* __restrict__ QKVl,
    __nv_bfloat16* __restrict__ Oh, __nv_bfloat16* __restrict__ Ol) {
  extern __shared__ __align__(16) char sm[];
  const uint32_t smb = smem_u32(sm);

  const int tid  = threadIdx.x;
  const int lane = tid & 31;
  const int wid  = tid >> 5;
  const int lr = lane & 15, lc = lane >> 4;
  const int g = lane >> 2, tig = lane & 3;
  const int r0 = wid * 16;
  const int srow = tid >> 4, sseg = tid & 15;
  const int nchan = NB * NC;

  auto stage128 = [&](uint32_t region, size_t goff) {
    const uint32_t sb = smb + region;
#pragma unroll
    for (int r = 0; r < 8; r++) {
      int row = srow + r * 16;
      uint32_t so = (uint32_t)(row * 272 + sseg * 16);
      cp_async16(sb + so,         QKVh + goff + row * 128 + sseg * 8);
      cp_async16(sb + 34816 + so, QKVl + goff + row * 128 + sseg * 8);
    }
  };
  auto qoff = [&](int q) {
    return ((size_t)(q >> 8) * 3 * NC + (q & 255)) * NHW;
  };

  const int c0 = blockIdx.x;
  stage128(AT_Q, qoff(c0));
  stage128(AT_K, qoff(c0) + (size_t)NC * NHW);
  CP_COMMIT();
  stage128(AT_V, qoff(c0) + (size_t)2 * NC * NHW);
  CP_COMMIT();

  for (int q = c0; q < nchan; q += gridDim.x) {
    const int qn = q + gridDim.x;

    CP_WAIT1();
    __syncthreads();

    float acc[16][4];
#pragma unroll
    for (int j = 0; j < 16; j++)
#pragma unroll
      for (int e = 0; e < 4; e++) acc[j][e] = 0.f;

#pragma unroll
    for (int ks = 0; ks < 8; ks++) {
      uint32_t qh[4], ql[4];
      uint32_t ao = smb + AT_Q + (uint32_t)((r0 + lr) * 272 + ks * 32 + lc * 16);
      ldsm_x4(qh, ao);
      ldsm_x4(ql, ao + 34816);
#pragma unroll
      for (int nt = 0; nt < 8; nt += 2) {
        uint32_t kh0[4], kl0[4], kh1[4], kl1[4];
        uint32_t bo0 = smb + AT_K + (uint32_t)((nt * 16 + lr) * 272 + ks * 32 + lc * 16);
        uint32_t bo1 = bo0 + 16 * 272;
        ldsm_x4(kh0, bo0);
        ldsm_x4(kl0, bo0 + 34816);
        ldsm_x4(kh1, bo1);
        ldsm_x4(kl1, bo1 + 34816);
        mma_bf16(acc[2 * nt],     qh, kh0[0], kh0[2]);
        mma_bf16(acc[2 * nt + 1], qh, kh0[1], kh0[3]);
        mma_bf16(acc[2 * nt + 2], qh, kh1[0], kh1[2]);
        mma_bf16(acc[2 * nt + 3], qh, kh1[1], kh1[3]);
        mma_bf16(acc[2 * nt],     qh, kl0[0], kl0[2]);
        mma_bf16(acc[2 * nt + 1], qh, kl0[1], kl0[3]);
        mma_bf16(acc[2 * nt + 2], qh, kl1[0], kl1[2]);
        mma_bf16(acc[2 * nt + 3], qh, kl1[1], kl1[3]);
        mma_bf16(acc[2 * nt],     ql, kh0[0], kh0[2]);
        mma_bf16(acc[2 * nt + 1], ql, kh0[1], kh0[3]);
        mma_bf16(acc[2 * nt + 2], ql, kh1[0], kh1[2]);
        mma_bf16(acc[2 * nt + 3], ql, kh1[1], kh1[3]);
      }
    }

    CP_WAIT0();
    __syncthreads();

    if (qn < nchan) {
      stage128(AT_Q, qoff(qn));
      stage128(AT_K, qoff(qn) + (size_t)NC * NHW);
    }
    CP_COMMIT();

    const float C = 0.42044820762685725f * 1.4426950408889634f;
    float sA = 0.f, sB = 0.f;
#pragma unroll
    for (int j = 0; j < 16; j++) {
      acc[j][0] = ex2(acc[j][0] * C);
      acc[j][1] = ex2(acc[j][1] * C);
      acc[j][2] = ex2(acc[j][2] * C);
      acc[j][3] = ex2(acc[j][3] * C);
      sA += acc[j][0] + acc[j][1];
      sB += acc[j][2] + acc[j][3];
    }

    uint32_t ph[8][4], pl[8][4];
#pragma unroll
    for (int ky = 0; ky < 8; ky++) {
      const int j0 = 2 * ky, j1 = 2 * ky + 1;
      ph[ky][0] = pack_hi(acc[j0][0], acc[j0][1]);
      ph[ky][1] = pack_hi(acc[j0][2], acc[j0][3]);
      ph[ky][2] = pack_hi(acc[j1][0], acc[j1][1]);
      ph[ky][3] = pack_hi(acc[j1][2], acc[j1][3]);
      pl[ky][0] = pack_lo(acc[j0][0], acc[j0][1]);
      pl[ky][1] = pack_lo(acc[j0][2], acc[j0][3]);
      pl[ky][2] = pack_lo(acc[j1][0], acc[j1][1]);
      pl[ky][3] = pack_lo(acc[j1][2], acc[j1][3]);
    }

    sA += __shfl_xor_sync(0xffffffffu, sA, 1);
    sA += __shfl_xor_sync(0xffffffffu, sA, 2);
    sB += __shfl_xor_sync(0xffffffffu, sB, 1);
    sB += __shfl_xor_sync(0xffffffffu, sB, 2);
    const float rA = 1.0f / sA, rB = 1.0f / sB;

    float oac[16][4];
#pragma unroll
    for (int j = 0; j < 16; j++)
#pragma unroll
      for (int e = 0; e < 4; e++) oac[j][e] = 0.f;

#pragma unroll
    for (int ky = 0; ky < 8; ky++) {
#pragma unroll
      for (int nt = 0; nt < 8; nt += 2) {
        uint32_t vh0[4], vl0[4], vh1[4], vl1[4];
        uint32_t bo0 = smb + AT_V + (uint32_t)((ky * 16 + lr) * 272 + nt * 32 + lc * 16);
        uint32_t bo1 = bo0 + 32;
        ldsm_x4_t(vh0, bo0);
        ldsm_x4_t(vl0, bo0 + 34816);
        ldsm_x4_t(vh1, bo1);
        ldsm_x4_t(vl1, bo1 + 34816);
        mma_bf16(oac[2 * nt],     ph[ky], vh0[0], vh0[1]);
        mma_bf16(oac[2 * nt + 1], ph[ky], vh0[2], vh0[3]);
        mma_bf16(oac[2 * nt + 2], ph[ky], vh1[0], vh1[1]);
        mma_bf16(oac[2 * nt + 3], ph[ky], vh1[2], vh1[3]);
        mma_bf16(oac[2 * nt],     ph[ky], vl0[0], vl0[1]);
        mma_bf16(oac[2 * nt + 1], ph[ky], vl0[2], vl0[3]);
        mma_bf16(oac[2 * nt + 2], ph[ky], vl1[0], vl1[1]);
        mma_bf16(oac[2 * nt + 3], ph[ky], vl1[2], vl1[3]);
        mma_bf16(oac[2 * nt],     pl[ky], vh0[0], vh0[1]);
        mma_bf16(oac[2 * nt + 1], pl[ky], vh0[2], vh0[3]);
        mma_bf16(oac[2 * nt + 2], pl[ky], vh1[0], vh1[1]);
        mma_bf16(oac[2 * nt + 3], pl[ky], vh1[2], vh1[3]);
      }
    }

    __syncthreads();
    if (qn < nchan)
      stage128(AT_V, qoff(qn) + (size_t)2 * NC * NHW);
    CP_COMMIT();

    const size_t ob = (size_t)q * NHW;
    const int row0 = r0 + g, row1 = r0 + g + 8;
#pragma unroll
    for (int j = 0; j < 16; j++) {
      int col = j * 8 + tig * 2;
      float v00 = oac[j][0] * rA, v01 = oac[j][1] * rA;
      float v10 = oac[j][2] * rB, v11 = oac[j][3] * rB;
      size_t o0a = ob + (size_t)row0 * 128 + col;
      size_t o1a = ob + (size_t)row1 * 128 + col;
      *(uint32_t*)(Oh + o0a) = pack_hi(v00, v01);
      *(uint32_t*)(Oh + o1a) = pack_hi(v10, v11);
      *(uint32_t*)(Ol + o0a) = pack_lo(v00, v01);
      *(uint32_t*)(Ol + o1a) = pack_lo(v10, v11);
    }
  }
}

// ---------------------------------------------------------------------------
extern "C" void kernel_launch(void* const* d_in, const int* in_sizes, int n_in,
                              void* d_out, int out_size) {
  const float* x  = (const float*)d_in[0];
  const float* wq = (const float*)d_in[1];
  const float* bq = (const float*)d_in[2];
  const float* wk = (const float*)d_in[3];
  const float* bk = (const float*)d_in[4];
  const float* wv = (const float*)d_in[5];
  const float* bv = (const float*)d_in[6];
  const float* wo = (const float*)d_in[7];
  const float* bo = (const float*)d_in[8];

  __nv_bfloat16 *xh, *xl, *qkvh, *qkvl, *ath, *atl, *wh, *wl, *wvhs;
  uint8_t *x8, *w8;
  float* bias;
  cudaGetSymbolAddress((void**)&xh,   g_x_hi);
  cudaGetSymbolAddress((void**)&xl,   g_x_lo);
  cudaGetSymbolAddress((void**)&x8,   g_x8);
  cudaGetSymbolAddress((void**)&qkvh, g_qkv_hi);
  cudaGetSymbolAddress((void**)&qkvl, g_qkv_lo);
  cudaGetSymbolAddress((void**)&ath,  g_att_hi);
  cudaGetSymbolAddress((void**)&atl,  g_att_lo);
  cudaGetSymbolAddress((void**)&wh,   g_w_hi);
  cudaGetSymbolAddress((void**)&wl,   g_w_lo);
  cudaGetSymbolAddress((void**)&wvhs, g_wv_his);
  cudaGetSymbolAddress((void**)&w8,   g_w8frag);
  cudaGetSymbolAddress((void**)&bias, g_bias);

  int nsm = 148;
  cudaDeviceGetAttribute(&nsm, cudaDevAttrMultiProcessorCount, 0);
  if (nsm > NB * NC) nsm = NB * NC;

  cudaFuncSetAttribute(gemm_mma,
                       cudaFuncAttributeMaxDynamicSharedMemorySize, SMEM_GEMM);
  cudaFuncSetAttribute(vgemm_mma,
                       cudaFuncAttributeMaxDynamicSharedMemorySize, SMEM_VGEMM);
  cudaFuncSetAttribute(attn_mma,
                       cudaFuncAttributeMaxDynamicSharedMemorySize, SMEM_ATTN);

  // Converters
  split_t<<<dim3(NHW / 64, NB), 256>>>(x, xh, xl, x8);
  convert_w<<<dim3(NC * NC / 256, 4), 256>>>(wq, wk, wv, wo, bq, bk, bv, bo, wh, wl);

  // QK projection (bf16 3-term) -> qkv[0..512)
  gemm_mma<<<dim3(4, NHW / 128, NB), 256, SMEM_GEMM>>>(
      xh, xl, wh, wl, bias, nullptr, qkvh, qkvl, 3 * NC);

  // V projection (bf16 main + fp8 corrections) -> qkv[512..768)
  vgemm_mma<<<dim3(2, NHW / 128, NB), 256, SMEM_VGEMM>>>(
      xh, x8, wvhs, w8, bias + 2 * NC, qkvh, qkvl);

  // Persistent tensor-core attention -> bf16 hi/lo
  attn_mma<<<nsm, 256, SMEM_ATTN>>>(qkvh, qkvl, ath, atl);

  // Output projection (bf16 3-term) -> fp32 d_out
  gemm_mma<<<dim3(2, NHW / 128, NB), 256, SMEM_GEMM>>>(
      ath, atl, wh + 3 * NC * NC, wl + 3 * NC * NC, bias + 3 * NC,
      (float*)d_out, nullptr, nullptr, NC);
}

// round 16
// speedup vs baseline: 1.0652x; 1.0652x over previous
#include <cuda_runtime.h>
#include <cuda_bf16.h>
#include <cuda_fp8.h>
#include <cstdint>
#include <math.h>

#define NB   8
#define NC   256
#define NH   128
#define NW   128
#define NHW  (NH * NW)        // 16384

// ---------------------------------------------------------------------------
// Scratch (device globals: allocation-guard safe; 16B-aligned for vector ops)
// ---------------------------------------------------------------------------
__device__ __align__(16) __nv_bfloat16 g_x_hi[(size_t)NB * NC * NHW];   // [b][c][n]
__device__ __align__(16) __nv_bfloat16 g_x_lo[(size_t)NB * NC * NHW];
__device__ __align__(16) uint8_t g_x8[(size_t)NB * NHW * 512];          // [b][n][k']
__device__ __align__(16) __nv_bfloat16 g_qkv_hi[(size_t)NB * 3 * NC * NHW];
__device__ __align__(16) __nv_bfloat16 g_qkv_lo[(size_t)NB * 3 * NC * NHW];
__device__ __align__(16) __nv_bfloat16 g_att_hi[(size_t)NB * NC * NHW];
__device__ __align__(16) __nv_bfloat16 g_att_lo[(size_t)NB * NC * NHW];
__device__ __align__(16) __nv_bfloat16 g_w_hi[4 * NC * NC];             // [o][c]
__device__ __align__(16) __nv_bfloat16 g_w_lo[4 * NC * NC];
__device__ __align__(16) __nv_bfloat16 g_wv_his[NC * NC];               // bf16(wv_hi)*512
__device__ __align__(16) uint8_t g_w8frag[16 * 16 * 32 * 16];           // V fp8 A-frags
__device__ __align__(16) float g_bias[4 * NC];

// ---------------------------------------------------------------------------
// PTX helpers
// ---------------------------------------------------------------------------
__device__ __forceinline__ uint32_t smem_u32(const void* p) {
  uint32_t a;
  asm("{ .reg .u64 t; cvta.to.shared.u64 t, %1; cvt.u32.u64 %0, t; }"
      : "=r"(a) : "l"(p));
  return a;
}
__device__ __forceinline__ void cp_async16(uint32_t sdst, const void* gsrc) {
  asm volatile("cp.async.cg.shared.global [%0], [%1], 16;"
               :: "r"(sdst), "l"(gsrc));
}
#define CP_COMMIT() asm volatile("cp.async.commit_group;" ::: "memory")
#define CP_WAIT0()  asm volatile("cp.async.wait_group 0;" ::: "memory")
#define CP_WAIT1()  asm volatile("cp.async.wait_group 1;" ::: "memory")

__device__ __forceinline__ void ldsm_x4(uint32_t* r, uint32_t addr) {
  asm volatile("ldmatrix.sync.aligned.m8n8.x4.shared.b16 {%0,%1,%2,%3}, [%4];"
               : "=r"(r[0]), "=r"(r[1]), "=r"(r[2]), "=r"(r[3]) : "r"(addr));
}
__device__ __forceinline__ void ldsm_x4_t(uint32_t* r, uint32_t addr) {
  asm volatile("ldmatrix.sync.aligned.m8n8.x4.trans.shared.b16 {%0,%1,%2,%3}, [%4];"
               : "=r"(r[0]), "=r"(r[1]), "=r"(r[2]), "=r"(r[3]) : "r"(addr));
}
__device__ __forceinline__ uint32_t lds32(uint32_t addr) {
  uint32_t v;
  asm volatile("ld.shared.b32 %0, [%1];" : "=r"(v) : "r"(addr));
  return v;
}
__device__ __forceinline__ void mma_bf16(float* d, const uint32_t* a,
                                         uint32_t b0, uint32_t b1) {
  asm volatile(
      "mma.sync.aligned.m16n8k16.row.col.f32.bf16.bf16.f32 "
      "{%0,%1,%2,%3}, {%4,%5,%6,%7}, {%8,%9}, {%0,%1,%2,%3};"
      : "+f"(d[0]), "+f"(d[1]), "+f"(d[2]), "+f"(d[3])
      : "r"(a[0]), "r"(a[1]), "r"(a[2]), "r"(a[3]), "r"(b0), "r"(b1));
}
__device__ __forceinline__ void mma_fp8(float* d, const uint32_t* a,
                                        uint32_t b0, uint32_t b1) {
  asm volatile(
      "mma.sync.aligned.m16n8k32.row.col.f32.e4m3.e4m3.f32 "
      "{%0,%1,%2,%3}, {%4,%5,%6,%7}, {%8,%9}, {%0,%1,%2,%3};"
      : "+f"(d[0]), "+f"(d[1]), "+f"(d[2]), "+f"(d[3])
      : "r"(a[0]), "r"(a[1]), "r"(a[2]), "r"(a[3]), "r"(b0), "r"(b1));
}
__device__ __forceinline__ float ex2(float x) {
  float r;
  asm("ex2.approx.f32 %0, %1;" : "=f"(r) : "f"(x));
  return r;
}
__device__ __forceinline__ uint32_t pack_hi(float a, float b) {
  __nv_bfloat162 p = {__float2bfloat16(a), __float2bfloat16(b)};
  return *(uint32_t*)&p;
}
__device__ __forceinline__ uint32_t pack_lo(float a, float b) {
  __nv_bfloat16 ha = __float2bfloat16(a), hb = __float2bfloat16(b);
  __nv_bfloat162 p = {__float2bfloat16(a - __bfloat162float(ha)),
                      __float2bfloat16(b - __bfloat162float(hb))};
  return *(uint32_t*)&p;
}
__device__ __forceinline__ uint8_t f8(float v) {
  return (uint8_t)__nv_cvt_float_to_fp8(v, __NV_SATFINITE, __NV_E4M3);
}

// ---------------------------------------------------------------------------
// Transposing converter: x fp32 [c][n] -> bf16 hi/lo [c][n] + fp8 [n][k']
// ---------------------------------------------------------------------------
__global__ __launch_bounds__(256) void split_t(
    const float* __restrict__ X,
    __nv_bfloat16* __restrict__ H, __nv_bfloat16* __restrict__ L,
    uint8_t* __restrict__ X8) {
  __shared__ float t[32][68];
  const int b  = blockIdx.y;
  const int n0 = blockIdx.x * 64;
  const int tid = threadIdx.x;
  const int r  = tid >> 3, sg = tid & 7;
  const int nn = tid >> 2, cs = tid & 3;

  for (int cc = 0; cc < 8; cc++) {
    const int c = cc * 32 + r;
    const size_t off = ((size_t)b * NC + c) * NHW + n0 + sg * 8;
    float4 v0 = *(const float4*)(X + off);
    float4 v1 = *(const float4*)(X + off + 4);
    *(uint4*)(H + off) = make_uint4(pack_hi(v0.x, v0.y), pack_hi(v0.z, v0.w),
                                    pack_hi(v1.x, v1.y), pack_hi(v1.z, v1.w));
    *(uint4*)(L + off) = make_uint4(pack_lo(v0.x, v0.y), pack_lo(v0.z, v0.w),
                                    pack_lo(v1.x, v1.y), pack_lo(v1.z, v1.w));
    *(float4*)(&t[r][sg * 8])     = v0;
    *(float4*)(&t[r][sg * 8 + 4]) = v1;
    __syncthreads();

    uint32_t lw0 = 0, lw1 = 0, hw0 = 0, hw1 = 0;
#pragma unroll
    for (int j = 0; j < 4; j++) {
      float v = t[cs * 8 + j][nn];
      float hf = __bfloat162float(__float2bfloat16(v));
      hw0 |= (uint32_t)f8(hf) << (8 * j);
      lw0 |= (uint32_t)f8((v - hf) * 512.0f) << (8 * j);
      float v2 = t[cs * 8 + 4 + j][nn];
      float hf2 = __bfloat162float(__float2bfloat16(v2));
      hw1 |= (uint32_t)f8(hf2) << (8 * j);
      lw1 |= (uint32_t)f8((v2 - hf2) * 512.0f) << (8 * j);
    }
    uint8_t* dst = X8 + ((size_t)b * NHW + n0 + nn) * 512 + cc * 32 + cs * 8;
    *(uint2*)(dst)       = make_uint2(lw0, lw1);   // fp8(xl*512)
    *(uint2*)(dst + 256) = make_uint2(hw0, hw1);   // fp8(xh)
    __syncthreads();
  }
}

// ---------------------------------------------------------------------------
// Weight converter: bf16 hi/lo for all 4; V extras: scaled-hi bf16 + fp8 frags
// ---------------------------------------------------------------------------
__global__ __launch_bounds__(256) void convert_w(
    const float* __restrict__ w0, const float* __restrict__ w1,
    const float* __restrict__ w2, const float* __restrict__ w3,
    const float* __restrict__ b0, const float* __restrict__ b1,
    const float* __restrict__ b2, const float* __restrict__ b3,
    __nv_bfloat16* __restrict__ H, __nv_bfloat16* __restrict__ L) {
  const float* ws[4] = {w0, w1, w2, w3};
  const float* bs[4] = {b0, b1, b2, b3};
  int m = blockIdx.y;
  int i = blockIdx.x * 256 + threadIdx.x;
  float v = ws[m][i];
  __nv_bfloat16 h = __float2bfloat16(v);
  float hf = __bfloat162float(h);
  H[m * NC * NC + i] = h;
  L[m * NC * NC + i] = __float2bfloat16(v - hf);
  if (blockIdx.x == 0) g_bias[m * NC + threadIdx.x] = bs[m][threadIdx.x];

  if (m == 2) {
    int o = i >> 8, c = i & 255;
    g_wv_his[i] = __float2bfloat16(hf * 512.0f);
    float lf = v - hf;
    auto fragoff = [](int o, int kp) {
      int s = kp >> 5, w = kp & 31;
      int half = (w >> 4) & 1, tt = (w >> 2) & 3, byt = w & 3;
      int gg = o & 7, up = (o >> 3) & 1, r16 = o >> 4;
      int reg = up + 2 * half;
      return (((r16 * 16 + s) * 32) + (gg * 4 + tt)) * 16 + reg * 4 + byt;
    };
    g_w8frag[fragoff(o, c)]       = f8(hf);            // pairs fp8(xl*512)
    g_w8frag[fragoff(o, c + 256)] = f8(lf * 512.0f);   // pairs fp8(xh)
  }
}

// ---------------------------------------------------------------------------
// mma.sync bf16-split GEMM (best measured, unchanged) — QK + out-proj
// ---------------------------------------------------------------------------
#define OFF_AH   0
#define OFF_AL   10240
#define OFF_BH   20480
#define OFF_BL   29184
#define BUF_BYTES 37888
#define SMEM_GEMM (3 * BUF_BYTES)

__global__ __launch_bounds__(256, 2) void gemm_mma(
    const __nv_bfloat16* __restrict__ Xh, const __nv_bfloat16* __restrict__ Xl,
    const __nv_bfloat16* __restrict__ Wh, const __nv_bfloat16* __restrict__ Wl,
    const float* __restrict__ bias, float* __restrict__ Yf,
    __nv_bfloat16* __restrict__ Yh, __nv_bfloat16* __restrict__ Yl,
    int ocnt) {
  extern __shared__ __align__(16) char sm[];
  const uint32_t smb = smem_u32(sm);

  const int tid  = threadIdx.x;
  const int lane = tid & 31;
  const int wid  = tid >> 5;
  const int wm   = wid & 3;
  const int wn   = wid >> 2;
  const int b    = blockIdx.z;
  const int o0   = blockIdx.x * 128;
  const int n0   = blockIdx.y * 128;

  const __nv_bfloat16* Xbh = Xh + (size_t)b * NC * NHW + n0;
  const __nv_bfloat16* Xbl = Xl + (size_t)b * NC * NHW + n0;
  const __nv_bfloat16* Wbh = Wh + (size_t)o0 * NC;
  const __nv_bfloat16* Wbl = Wl + (size_t)o0 * NC;

  const int a_row0 = tid >> 2, a_seg = tid & 3;
  const int b_row0 = tid >> 4, b_seg = tid & 15;

  float acc[2][8][4];
#pragma unroll
  for (int mt = 0; mt < 2; mt++)
#pragma unroll
    for (int nt = 0; nt < 8; nt++)
#pragma unroll
      for (int e = 0; e < 4; e++) acc[mt][nt][e] = 0.f;

  const int lr = lane & 15, lc = lane >> 4;
  uint32_t a_base = (uint32_t)((wm * 32 + lr) * 80 + lc * 16);
  uint32_t b_base = (uint32_t)(lr * 272 + wn * 128 + lc * 16);

  auto stage = [&](int it, int slot) {
    const int c0 = it * 32;
    const uint32_t sb = smb + slot * BUF_BYTES;
#pragma unroll
    for (int r = 0; r < 2; r++) {
      int row = a_row0 + r * 64;
      uint32_t so = (uint32_t)(row * 80 + a_seg * 16);
      cp_async16(sb + OFF_AH + so, Wbh + (size_t)row * NC + c0 + a_seg * 8);
      cp_async16(sb + OFF_AL + so, Wbl + (size_t)row * NC + c0 + a_seg * 8);
    }
#pragma unroll
    for (int r = 0; r < 2; r++) {
      int row = b_row0 + r * 16;
      uint32_t so = (uint32_t)(row * 272 + b_seg * 16);
      cp_async16(sb + OFF_BH + so, Xbh + (size_t)(c0 + row) * NHW + b_seg * 8);
      cp_async16(sb + OFF_BL + so, Xbl + (size_t)(c0 + row) * NHW + b_seg * 8);
    }
    CP_COMMIT();
  };

  stage(0, 0);
  stage(1, 1);

  int slot = 0;
  for (int it = 0; it < 8; it++) {
    if (it < 7) { CP_WAIT1(); } else { CP_WAIT0(); }
    __syncthreads();
    int pslot = slot + 2 >= 3 ? slot - 1 : slot + 2;
    if (it + 2 < 8) stage(it + 2, pslot);

    const uint32_t sb = smb + slot * BUF_BYTES;
#pragma unroll
    for (int ks = 0; ks < 2; ks++) {
      uint32_t ah[2][4], al[2][4];
#pragma unroll
      for (int mt = 0; mt < 2; mt++) {
        uint32_t ao = sb + a_base + (uint32_t)(mt * 16 * 80 + ks * 32);
        ldsm_x4(ah[mt], ao + OFF_AH);
        ldsm_x4(al[mt], ao + OFF_AL);
      }
#pragma unroll
      for (int nt2 = 0; nt2 < 4; nt2++) {
        uint32_t bh[4], bl[4];
        uint32_t bo = sb + b_base + (uint32_t)(ks * 16 * 272 + nt2 * 32);
        ldsm_x4_t(bh, bo + OFF_BH);
        ldsm_x4_t(bl, bo + OFF_BL);
        mma_bf16(acc[0][nt2 * 2],     ah[0], bh[0], bh[1]);
        mma_bf16(acc[0][nt2 * 2 + 1], ah[0], bh[2], bh[3]);
        mma_bf16(acc[1][nt2 * 2],     ah[1], bh[0], bh[1]);
        mma_bf16(acc[1][nt2 * 2 + 1], ah[1], bh[2], bh[3]);
        mma_bf16(acc[0][nt2 * 2],     ah[0], bl[0], bl[1]);
        mma_bf16(acc[0][nt2 * 2 + 1], ah[0], bl[2], bl[3]);
        mma_bf16(acc[1][nt2 * 2],     ah[1], bl[0], bl[1]);
        mma_bf16(acc[1][nt2 * 2 + 1], ah[1], bl[2], bl[3]);
        mma_bf16(acc[0][nt2 * 2],     al[0], bh[0], bh[1]);
        mma_bf16(acc[0][nt2 * 2 + 1], al[0], bh[2], bh[3]);
        mma_bf16(acc[1][nt2 * 2],     al[1], bh[0], bh[1]);
        mma_bf16(acc[1][nt2 * 2 + 1], al[1], bh[2], bh[3]);
      }
    }
    slot = slot + 1 >= 3 ? 0 : slot + 1;
  }
  __syncthreads();

#pragma unroll
  for (int mt = 0; mt < 2; mt++) {
    int o = o0 + wm * 32 + mt * 16 + (lane >> 2);
    float bv0 = __ldg(bias + o);
    float bv1 = __ldg(bias + o + 8);
#pragma unroll
    for (int nt = 0; nt < 8; nt++) {
      int n = n0 + wn * 64 + nt * 8 + (lane & 3) * 2;
      float v00 = acc[mt][nt][0] + bv0, v01 = acc[mt][nt][1] + bv0;
      float v10 = acc[mt][nt][2] + bv1, v11 = acc[mt][nt][3] + bv1;
      size_t off0 = ((size_t)b * ocnt + o) * NHW + n;
      size_t off1 = ((size_t)b * ocnt + o + 8) * NHW + n;
      if (Yf) {
        *(float2*)(Yf + off0) = make_float2(v00, v01);
        *(float2*)(Yf + off1) = make_float2(v10, v11);
      } else {
        *(uint32_t*)(Yh + off0) = pack_hi(v00, v01);
        *(uint32_t*)(Yh + off1) = pack_hi(v10, v11);
        *(uint32_t*)(Yl + off0) = pack_lo(v00, v01);
        *(uint32_t*)(Yl + off1) = pack_lo(v10, v11);
      }
    }
  }
}

// ---------------------------------------------------------------------------
// V-projection GEMM: main bf16 (W*512) + ONE fp8 pass for both corrections.
// X8 slabs staged through smem (coalesced cp.async; 80B row stride =>
// 16B-aligned dsts and conflict-free LDS reads). W8 frags via coalesced LDG.
// ---------------------------------------------------------------------------
#define V_OFF_A   0
#define V_OFF_B   10240
#define V_OFF_X8  18944
#define V_BUF     29184           // A 10240 + B 8704 + X8 128*80
#define SMEM_VGEMM (3 * V_BUF)    // 87552 (x2 CTA = 175104 <= SM smem)

__global__ __launch_bounds__(256, 2) void vgemm_mma(
    const __nv_bfloat16* __restrict__ Xh, const uint8_t* __restrict__ X8,
    const __nv_bfloat16* __restrict__ Whs, const uint8_t* __restrict__ W8,
    const float* __restrict__ bias,
    __nv_bfloat16* __restrict__ Yh, __nv_bfloat16* __restrict__ Yl) {
  extern __shared__ __align__(16) char sm[];
  const uint32_t smb = smem_u32(sm);

  const int tid  = threadIdx.x;
  const int lane = tid & 31;
  const int wid  = tid >> 5;
  const int wm   = wid & 3;
  const int wn   = wid >> 2;
  const int b    = blockIdx.z;
  const int o0   = blockIdx.x * 128;
  const int n0   = blockIdx.y * 128;

  const __nv_bfloat16* Xbh = Xh + (size_t)b * NC * NHW + n0;
  const __nv_bfloat16* Wb  = Whs + (size_t)o0 * NC;
  const uint8_t* X8b = X8 + ((size_t)b * NHW + n0) * 512;

  const int a_row0 = tid >> 2, a_seg = tid & 3;
  const int b_row0 = tid >> 4, b_seg = tid & 15;
  const int x_row0 = tid >> 1, x_seg = tid & 1;   // X8: 128 rows x 4 segs of 16B

  float acc[2][8][4];
#pragma unroll
  for (int mt = 0; mt < 2; mt++)
#pragma unroll
    for (int nt = 0; nt < 8; nt++)
#pragma unroll
      for (int e = 0; e < 4; e++) acc[mt][nt][e] = 0.f;

  const int lr = lane & 15, lc = lane >> 4;
  const int g = lane >> 2, tig = lane & 3;
  uint32_t a_base = (uint32_t)((wm * 32 + lr) * 80 + lc * 16);
  uint32_t b_base = (uint32_t)(lr * 272 + wn * 128 + lc * 16);
  const int r16b = (o0 >> 4) + wm * 2;

  auto stage = [&](int it, int slot) {
    const int c0 = it * 32;
    const uint32_t sb = smb + slot * V_BUF;
#pragma unroll
    for (int r = 0; r < 2; r++) {
      int row = a_row0 + r * 64;
      cp_async16(sb + V_OFF_A + (uint32_t)(row * 80 + a_seg * 16),
                 Wb + (size_t)row * NC + c0 + a_seg * 8);
    }
#pragma unroll
    for (int r = 0; r < 2; r++) {
      int row = b_row0 + r * 16;
      cp_async16(sb + V_OFF_B + (uint32_t)(row * 272 + b_seg * 16),
                 Xbh + (size_t)(c0 + row) * NHW + b_seg * 8);
    }
    // X8 slabs for this chunk: bytes [it*64, it*64+64) of rows n0..n0+127
#pragma unroll
    for (int r = 0; r < 2; r++) {
      int seg = x_seg + r * 2;       // 0..3
      cp_async16(sb + V_OFF_X8 + (uint32_t)(x_row0 * 80 + seg * 16),
                 X8b + (size_t)x_row0 * 512 + it * 64 + seg * 16);
    }
    CP_COMMIT();
  };

  stage(0, 0);
  stage(1, 1);

  int slot = 0;
  for (int it = 0; it < 8; it++) {
    if (it < 7) { CP_WAIT1(); } else { CP_WAIT0(); }
    __syncthreads();
    int pslot = slot + 2 >= 3 ? slot - 1 : slot + 2;
    if (it + 2 < 8) stage(it + 2, pslot);

    const uint32_t sb = smb + slot * V_BUF;
#pragma unroll
    for (int ks = 0; ks < 2; ks++) {
      const int s = it * 2 + ks;     // global fp8 slab 0..15
      uint4 af0 = *(const uint4*)(W8 + (size_t)(((r16b + 0) * 16 + s) * 32 + lane) * 16);
      uint4 af1 = *(const uint4*)(W8 + (size_t)(((r16b + 1) * 16 + s) * 32 + lane) * 16);

      // fp8 B fragments from smem (conflict-free: bank = (20*row+tig)%32)
      uint32_t b0v[8], b1v[8];
#pragma unroll
      for (int nt = 0; nt < 8; nt++) {
        uint32_t xo = sb + V_OFF_X8 +
            (uint32_t)((wn * 64 + nt * 8 + g) * 80 + ks * 32 + 4 * tig);
        b0v[nt] = lds32(xo);
        b1v[nt] = lds32(xo + 16);
      }

      // main bf16 (hi*hi at 512x scale)
      uint32_t ah[2][4];
#pragma unroll
      for (int mt = 0; mt < 2; mt++)
        ldsm_x4(ah[mt], sb + V_OFF_A + a_base + (uint32_t)(mt * 16 * 80 + ks * 32));
#pragma unroll
      for (int nt2 = 0; nt2 < 4; nt2++) {
        uint32_t bh[4];
        ldsm_x4_t(bh, sb + V_OFF_B + b_base + (uint32_t)(ks * 16 * 272 + nt2 * 32));
        mma_bf16(acc[0][nt2 * 2],     ah[0], bh[0], bh[1]);
        mma_bf16(acc[0][nt2 * 2 + 1], ah[0], bh[2], bh[3]);
        mma_bf16(acc[1][nt2 * 2],     ah[1], bh[0], bh[1]);
        mma_bf16(acc[1][nt2 * 2 + 1], ah[1], bh[2], bh[3]);
      }

      // fp8 corrections (both split terms in one k32 pass)
#pragma unroll
      for (int nt = 0; nt < 8; nt++) {
        mma_fp8(acc[0][nt], (const uint32_t*)&af0, b0v[nt], b1v[nt]);
        mma_fp8(acc[1][nt], (const uint32_t*)&af1, b0v[nt], b1v[nt]);
      }
    }
    slot = slot + 1 >= 3 ? 0 : slot + 1;
  }
  __syncthreads();

  const float INV = 1.0f / 512.0f;
#pragma unroll
  for (int mt = 0; mt < 2; mt++) {
    int o = o0 + wm * 32 + mt * 16 + g;
    float bv0 = __ldg(bias + o);
    float bv1 = __ldg(bias + o + 8);
#pragma unroll
    for (int nt = 0; nt < 8; nt++) {
      int n = n0 + wn * 64 + nt * 8 + tig * 2;
      float v00 = acc[mt][nt][0] * INV + bv0, v01 = acc[mt][nt][1] * INV + bv0;
      float v10 = acc[mt][nt][2] * INV + bv1, v11 = acc[mt][nt][3] * INV + bv1;
      size_t off0 = ((size_t)b * (3 * NC) + 512 + o) * NHW + n;
      size_t off1 = off0 + (size_t)8 * NHW;
      *(uint32_t*)(Yh + off0) = pack_hi(v00, v01);
      *(uint32_t*)(Yh + off1) = pack_hi(v10, v11);
      *(uint32_t*)(Yl + off0) = pack_lo(v00, v01);
      *(uint32_t*)(Yl + off1) = pack_lo(v10, v11);
    }
  }
}

// ---------------------------------------------------------------------------
// Persistent tensor-core attention (R11 best — unchanged)
// ---------------------------------------------------------------------------
#define AT_Q 0
#define AT_K 69632
#define AT_V 139264
#define SMEM_ATTN 208896

__global__ __launch_bounds__(256) void attn_mma(
    const __nv_bfloat16* __restrict__ QKVh,
    const __nv_bfloat16* __restrict__ QKVl,
    __nv_bfloat16* __restrict__ Oh, __nv_bfloat16* __restrict__ Ol) {
  extern __shared__ __align__(16) char sm[];
  const uint32_t smb = smem_u32(sm);

  const int tid  = threadIdx.x;
  const int lane = tid & 31;
  const int wid  = tid >> 5;
  const int lr = lane & 15, lc = lane >> 4;
  const int g = lane >> 2, tig = lane & 3;
  const int r0 = wid * 16;
  const int srow = tid >> 4, sseg = tid & 15;
  const int nchan = NB * NC;

  auto stage128 = [&](uint32_t region, size_t goff) {
    const uint32_t sb = smb + region;
#pragma unroll
    for (int r = 0; r < 8; r++) {
      int row = srow + r * 16;
      uint32_t so = (uint32_t)(row * 272 + sseg * 16);
      cp_async16(sb + so,         QKVh + goff + row * 128 + sseg * 8);
      cp_async16(sb + 34816 + so, QKVl + goff + row * 128 + sseg * 8);
    }
  };
  auto qoff = [&](int q) {
    return ((size_t)(q >> 8) * 3 * NC + (q & 255)) * NHW;
  };

  const int c0 = blockIdx.x;
  stage128(AT_Q, qoff(c0));
  stage128(AT_K, qoff(c0) + (size_t)NC * NHW);
  CP_COMMIT();
  stage128(AT_V, qoff(c0) + (size_t)2 * NC * NHW);
  CP_COMMIT();

  for (int q = c0; q < nchan; q += gridDim.x) {
    const int qn = q + gridDim.x;

    CP_WAIT1();
    __syncthreads();

    float acc[16][4];
#pragma unroll
    for (int j = 0; j < 16; j++)
#pragma unroll
      for (int e = 0; e < 4; e++) acc[j][e] = 0.f;

#pragma unroll
    for (int ks = 0; ks < 8; ks++) {
      uint32_t qh[4], ql[4];
      uint32_t ao = smb + AT_Q + (uint32_t)((r0 + lr) * 272 + ks * 32 + lc * 16);
      ldsm_x4(qh, ao);
      ldsm_x4(ql, ao + 34816);
#pragma unroll
      for (int nt = 0; nt < 8; nt += 2) {
        uint32_t kh0[4], kl0[4], kh1[4], kl1[4];
        uint32_t bo0 = smb + AT_K + (uint32_t)((nt * 16 + lr) * 272 + ks * 32 + lc * 16);
        uint32_t bo1 = bo0 + 16 * 272;
        ldsm_x4(kh0, bo0);
        ldsm_x4(kl0, bo0 + 34816);
        ldsm_x4(kh1, bo1);
        ldsm_x4(kl1, bo1 + 34816);
        mma_bf16(acc[2 * nt],     qh, kh0[0], kh0[2]);
        mma_bf16(acc[2 * nt + 1], qh, kh0[1], kh0[3]);
        mma_bf16(acc[2 * nt + 2], qh, kh1[0], kh1[2]);
        mma_bf16(acc[2 * nt + 3], qh, kh1[1], kh1[3]);
        mma_bf16(acc[2 * nt],     qh, kl0[0], kl0[2]);
        mma_bf16(acc[2 * nt + 1], qh, kl0[1], kl0[3]);
        mma_bf16(acc[2 * nt + 2], qh, kl1[0], kl1[2]);
        mma_bf16(acc[2 * nt + 3], qh, kl1[1], kl1[3]);
        mma_bf16(acc[2 * nt],     ql, kh0[0], kh0[2]);
        mma_bf16(acc[2 * nt + 1], ql, kh0[1], kh0[3]);
        mma_bf16(acc[2 * nt + 2], ql, kh1[0], kh1[2]);
        mma_bf16(acc[2 * nt + 3], ql, kh1[1], kh1[3]);
      }
    }

    CP_WAIT0();
    __syncthreads();

    if (qn < nchan) {
      stage128(AT_Q, qoff(qn));
      stage128(AT_K, qoff(qn) + (size_t)NC * NHW);
    }
    CP_COMMIT();

    const float C = 0.42044820762685725f * 1.4426950408889634f;
    float sA = 0.f, sB = 0.f;
#pragma unroll
    for (int j = 0; j < 16; j++) {
      acc[j][0] = ex2(acc[j][0] * C);
      acc[j][1] = ex2(acc[j][1] * C);
      acc[j][2] = ex2(acc[j][2] * C);
      acc[j][3] = ex2(acc[j][3] * C);
      sA += acc[j][0] + acc[j][1];
      sB += acc[j][2] + acc[j][3];
    }

    uint32_t ph[8][4], pl[8][4];
#pragma unroll
    for (int ky = 0; ky < 8; ky++) {
      const int j0 = 2 * ky, j1 = 2 * ky + 1;
      ph[ky][0] = pack_hi(acc[j0][0], acc[j0][1]);
      ph[ky][1] = pack_hi(acc[j0][2], acc[j0][3]);
      ph[ky][2] = pack_hi(acc[j1][0], acc[j1][1]);
      ph[ky][3] = pack_hi(acc[j1][2], acc[j1][3]);
      pl[ky][0] = pack_lo(acc[j0][0], acc[j0][1]);
      pl[ky][1] = pack_lo(acc[j0][2], acc[j0][3]);
      pl[ky][2] = pack_lo(acc[j1][0], acc[j1][1]);
      pl[ky][3] = pack_lo(acc[j1][2], acc[j1][3]);
    }

    sA += __shfl_xor_sync(0xffffffffu, sA, 1);
    sA += __shfl_xor_sync(0xffffffffu, sA, 2);
    sB += __shfl_xor_sync(0xffffffffu, sB, 1);
    sB += __shfl_xor_sync(0xffffffffu, sB, 2);
    const float rA = 1.0f / sA, rB = 1.0f / sB;

    float oac[16][4];
#pragma unroll
    for (int j = 0; j < 16; j++)
#pragma unroll
      for (int e = 0; e < 4; e++) oac[j][e] = 0.f;

#pragma unroll
    for (int ky = 0; ky < 8; ky++) {
#pragma unroll
      for (int nt = 0; nt < 8; nt += 2) {
        uint32_t vh0[4], vl0[4], vh1[4], vl1[4];
        uint32_t bo0 = smb + AT_V + (uint32_t)((ky * 16 + lr) * 272 + nt * 32 + lc * 16);
        uint32_t bo1 = bo0 + 32;
        ldsm_x4_t(vh0, bo0);
        ldsm_x4_t(vl0, bo0 + 34816);
        ldsm_x4_t(vh1, bo1);
        ldsm_x4_t(vl1, bo1 + 34816);
        mma_bf16(oac[2 * nt],     ph[ky], vh0[0], vh0[1]);
        mma_bf16(oac[2 * nt + 1], ph[ky], vh0[2], vh0[3]);
        mma_bf16(oac[2 * nt + 2], ph[ky], vh1[0], vh1[1]);
        mma_bf16(oac[2 * nt + 3], ph[ky], vh1[2], vh1[3]);
        mma_bf16(oac[2 * nt],     ph[ky], vl0[0], vl0[1]);
        mma_bf16(oac[2 * nt + 1], ph[ky], vl0[2], vl0[3]);
        mma_bf16(oac[2 * nt + 2], ph[ky], vl1[0], vl1[1]);
        mma_bf16(oac[2 * nt + 3], ph[ky], vl1[2], vl1[3]);
        mma_bf16(oac[2 * nt],     pl[ky], vh0[0], vh0[1]);
        mma_bf16(oac[2 * nt + 1], pl[ky], vh0[2], vh0[3]);
        mma_bf16(oac[2 * nt + 2], pl[ky], vh1[0], vh1[1]);
        mma_bf16(oac[2 * nt + 3], pl[ky], vh1[2], vh1[3]);
      }
    }

    __syncthreads();
    if (qn < nchan)
      stage128(AT_V, qoff(qn) + (size_t)2 * NC * NHW);
    CP_COMMIT();

    const size_t ob = (size_t)q * NHW;
    const int row0 = r0 + g, row1 = r0 + g + 8;
#pragma unroll
    for (int j = 0; j < 16; j++) {
      int col = j * 8 + tig * 2;
      float v00 = oac[j][0] * rA, v01 = oac[j][1] * rA;
      float v10 = oac[j][2] * rB, v11 = oac[j][3] * rB;
      size_t o0a = ob + (size_t)row0 * 128 + col;
      size_t o1a = ob + (size_t)row1 * 128 + col;
      *(uint32_t*)(Oh + o0a) = pack_hi(v00, v01);
      *(uint32_t*)(Oh + o1a) = pack_hi(v10, v11);
      *(uint32_t*)(Ol + o0a) = pack_lo(v00, v01);
      *(uint32_t*)(Ol + o1a) = pack_lo(v10, v11);
    }
  }
}

// ---------------------------------------------------------------------------
extern "C" void kernel_launch(void* const* d_in, const int* in_sizes, int n_in,
                              void* d_out, int out_size) {
  const float* x  = (const float*)d_in[0];
  const float* wq = (const float*)d_in[1];
  const float* bq = (const float*)d_in[2];
  const float* wk = (const float*)d_in[3];
  const float* bk = (const float*)d_in[4];
  const float* wv = (const float*)d_in[5];
  const float* bv = (const float*)d_in[6];
  const float* wo = (const float*)d_in[7];
  const float* bo = (const float*)d_in[8];

  __nv_bfloat16 *xh, *xl, *qkvh, *qkvl, *ath, *atl, *wh, *wl, *wvhs;
  uint8_t *x8, *w8;
  float* bias;
  cudaGetSymbolAddress((void**)&xh,   g_x_hi);
  cudaGetSymbolAddress((void**)&xl,   g_x_lo);
  cudaGetSymbolAddress((void**)&x8,   g_x8);
  cudaGetSymbolAddress((void**)&qkvh, g_qkv_hi);
  cudaGetSymbolAddress((void**)&qkvl, g_qkv_lo);
  cudaGetSymbolAddress((void**)&ath,  g_att_hi);
  cudaGetSymbolAddress((void**)&atl,  g_att_lo);
  cudaGetSymbolAddress((void**)&wh,   g_w_hi);
  cudaGetSymbolAddress((void**)&wl,   g_w_lo);
  cudaGetSymbolAddress((void**)&wvhs, g_wv_his);
  cudaGetSymbolAddress((void**)&w8,   g_w8frag);
  cudaGetSymbolAddress((void**)&bias, g_bias);

  int nsm = 148;
  cudaDeviceGetAttribute(&nsm, cudaDevAttrMultiProcessorCount, 0);
  if (nsm > NB * NC) nsm = NB * NC;

  cudaFuncSetAttribute(gemm_mma,
                       cudaFuncAttributeMaxDynamicSharedMemorySize, SMEM_GEMM);
  cudaFuncSetAttribute(vgemm_mma,
                       cudaFuncAttributeMaxDynamicSharedMemorySize, SMEM_VGEMM);
  cudaFuncSetAttribute(attn_mma,
                       cudaFuncAttributeMaxDynamicSharedMemorySize, SMEM_ATTN);

  // Converters
  split_t<<<dim3(NHW / 64, NB), 256>>>(x, xh, xl, x8);
  convert_w<<<dim3(NC * NC / 256, 4), 256>>>(wq, wk, wv, wo, bq, bk, bv, bo, wh, wl);

  // QK projection (bf16 3-term) -> qkv[0..512)
  gemm_mma<<<dim3(4, NHW / 128, NB), 256, SMEM_GEMM>>>(
      xh, xl, wh, wl, bias, nullptr, qkvh, qkvl, 3 * NC);

  // V projection (bf16 main + fp8 corrections) -> qkv[512..768)
  vgemm_mma<<<dim3(2, NHW / 128, NB), 256, SMEM_VGEMM>>>(
      xh, x8, wvhs, w8, bias + 2 * NC, qkvh, qkvl);

  // Persistent tensor-core attention -> bf16 hi/lo
  attn_mma<<<nsm, 256, SMEM_ATTN>>>(qkvh, qkvl, ath, atl);

  // Output projection (bf16 3-term) -> fp32 d_out
  gemm_mma<<<dim3(2, NHW / 128, NB), 256, SMEM_GEMM>>>(
      ath, atl, wh + 3 * NC * NC, wl + 3 * NC * NC, bias + 3 * NC,
      (float*)d_out, nullptr, nullptr, NC);
}

// round 17
// speedup vs baseline: 1.1346x; 1.0651x over previous
#include <cuda_runtime.h>
#include <cuda_bf16.h>
#include <cstdint>
#include <math.h>

#define NB   8
#define NC   256
#define NH   128
#define NW   128
#define NHW  (NH * NW)        // 16384

// ---------------------------------------------------------------------------
// Scratch (device globals: allocation-guard safe; 16B-aligned)
// ---------------------------------------------------------------------------
__device__ __align__(16) __nv_bfloat16 g_x_hi[(size_t)NB * NC * NHW];   // [b][c][n]
__device__ __align__(16) __nv_bfloat16 g_x_lo[(size_t)NB * NC * NHW];
__device__ __align__(16) __nv_bfloat16 g_qkv_hi[(size_t)NB * 3 * NC * NHW];
__device__ __align__(16) __nv_bfloat16 g_qkv_lo[(size_t)NB * 3 * NC * NHW];
__device__ __align__(16) __nv_bfloat16 g_att_hi[(size_t)NB * NC * NHW];
__device__ __align__(16) __nv_bfloat16 g_att_lo[(size_t)NB * NC * NHW];
__device__ __align__(16) __nv_bfloat16 g_w_hi[4 * NC * NC];             // [o][c]
__device__ __align__(16) __nv_bfloat16 g_w_lo[4 * NC * NC];
__device__ __align__(16) float g_bias[4 * NC];

// ---------------------------------------------------------------------------
// PTX helpers (sm_80-baseline tensor core path; valid on compute_103)
// ---------------------------------------------------------------------------
__device__ __forceinline__ uint32_t smem_u32(const void* p) {
  uint32_t a;
  asm("{ .reg .u64 t; cvta.to.shared.u64 t, %1; cvt.u32.u64 %0, t; }"
      : "=r"(a) : "l"(p));
  return a;
}
__device__ __forceinline__ void cp_async16(uint32_t sdst, const void* gsrc) {
  asm volatile("cp.async.cg.shared.global [%0], [%1], 16;"
               :: "r"(sdst), "l"(gsrc));
}
#define CP_COMMIT() asm volatile("cp.async.commit_group;" ::: "memory")
#define CP_WAIT0()  asm volatile("cp.async.wait_group 0;" ::: "memory")
#define CP_WAIT1()  asm volatile("cp.async.wait_group 1;" ::: "memory")

__device__ __forceinline__ void ldsm_x4(uint32_t* r, uint32_t addr) {
  asm volatile("ldmatrix.sync.aligned.m8n8.x4.shared.b16 {%0,%1,%2,%3}, [%4];"
               : "=r"(r[0]), "=r"(r[1]), "=r"(r[2]), "=r"(r[3]) : "r"(addr));
}
__device__ __forceinline__ void ldsm_x4_t(uint32_t* r, uint32_t addr) {
  asm volatile("ldmatrix.sync.aligned.m8n8.x4.trans.shared.b16 {%0,%1,%2,%3}, [%4];"
               : "=r"(r[0]), "=r"(r[1]), "=r"(r[2]), "=r"(r[3]) : "r"(addr));
}
__device__ __forceinline__ void mma_bf16(float* d, const uint32_t* a,
                                         uint32_t b0, uint32_t b1) {
  asm volatile(
      "mma.sync.aligned.m16n8k16.row.col.f32.bf16.bf16.f32 "
      "{%0,%1,%2,%3}, {%4,%5,%6,%7}, {%8,%9}, {%0,%1,%2,%3};"
      : "+f"(d[0]), "+f"(d[1]), "+f"(d[2]), "+f"(d[3])
      : "r"(a[0]), "r"(a[1]), "r"(a[2]), "r"(a[3]), "r"(b0), "r"(b1));
}
__device__ __forceinline__ float ex2(float x) {
  float r;
  asm("ex2.approx.f32 %0, %1;" : "=f"(r) : "f"(x));
  return r;
}
__device__ __forceinline__ uint32_t pack_hi(float a, float b) {
  __nv_bfloat162 p = {__float2bfloat16(a), __float2bfloat16(b)};
  return *(uint32_t*)&p;
}
__device__ __forceinline__ uint32_t pack_lo(float a, float b) {
  __nv_bfloat16 ha = __float2bfloat16(a), hb = __float2bfloat16(b);
  __nv_bfloat162 p = {__float2bfloat16(a - __bfloat162float(ha)),
                      __float2bfloat16(b - __bfloat162float(hb))};
  return *(uint32_t*)&p;
}

// ---------------------------------------------------------------------------
// Elementwise bf16 split: fp32 -> hi + lo (same layout)
// ---------------------------------------------------------------------------
__global__ __launch_bounds__(256) void split_f32(
    const float* __restrict__ X, __nv_bfloat16* __restrict__ H,
    __nv_bfloat16* __restrict__ L) {
  int i = blockIdx.x * 256 + threadIdx.x;
  float4 v = ((const float4*)X)[i];
  ((uint2*)H)[i] = make_uint2(pack_hi(v.x, v.y), pack_hi(v.z, v.w));
  ((uint2*)L)[i] = make_uint2(pack_lo(v.x, v.y), pack_lo(v.z, v.w));
}

__global__ __launch_bounds__(256) void convert_w(
    const float* __restrict__ w0, const float* __restrict__ w1,
    const float* __restrict__ w2, const float* __restrict__ w3,
    const float* __restrict__ b0, const float* __restrict__ b1,
    const float* __restrict__ b2, const float* __restrict__ b3,
    __nv_bfloat16* __restrict__ H, __nv_bfloat16* __restrict__ L) {
  const float* ws[4] = {w0, w1, w2, w3};
  const float* bs[4] = {b0, b1, b2, b3};
  int m = blockIdx.y;
  int i = blockIdx.x * 256 + threadIdx.x;
  float v = ws[m][i];
  __nv_bfloat16 h = __float2bfloat16(v);
  H[m * NC * NC + i] = h;
  L[m * NC * NC + i] = __float2bfloat16(v - __bfloat162float(h));
  if (blockIdx.x == 0) g_bias[m * NC + threadIdx.x] = bs[m][threadIdx.x];
}

// ---------------------------------------------------------------------------
// mma.sync bf16-split GEMM: D[o][n] = sum_c W[o][c] * X[c][n] + bias[o]
// CTA 128x128, K chunks 32, 3-stage cp.async ring, 8 warps (4 o x 2 n),
// 2 CTAs/SM. Best-measured configuration (R11).
// ---------------------------------------------------------------------------
#define OFF_AH   0
#define OFF_AL   10240
#define OFF_BH   20480
#define OFF_BL   29184
#define BUF_BYTES 37888
#define SMEM_GEMM (3 * BUF_BYTES)

__global__ __launch_bounds__(256, 2) void gemm_mma(
    const __nv_bfloat16* __restrict__ Xh, const __nv_bfloat16* __restrict__ Xl,
    const __nv_bfloat16* __restrict__ Wh, const __nv_bfloat16* __restrict__ Wl,
    const float* __restrict__ bias, float* __restrict__ Yf,
    __nv_bfloat16* __restrict__ Yh, __nv_bfloat16* __restrict__ Yl,
    int ocnt) {
  extern __shared__ __align__(16) char sm[];
  const uint32_t smb = smem_u32(sm);

  const int tid  = threadIdx.x;
  const int lane = tid & 31;
  const int wid  = tid >> 5;
  const int wm   = wid & 3;
  const int wn   = wid >> 2;
  const int b    = blockIdx.z;
  const int o0   = blockIdx.x * 128;
  const int n0   = blockIdx.y * 128;

  const __nv_bfloat16* Xbh = Xh + (size_t)b * NC * NHW + n0;
  const __nv_bfloat16* Xbl = Xl + (size_t)b * NC * NHW + n0;
  const __nv_bfloat16* Wbh = Wh + (size_t)o0 * NC;
  const __nv_bfloat16* Wbl = Wl + (size_t)o0 * NC;

  const int a_row0 = tid >> 2, a_seg = tid & 3;
  const int b_row0 = tid >> 4, b_seg = tid & 15;

  float acc[2][8][4];
#pragma unroll
  for (int mt = 0; mt < 2; mt++)
#pragma unroll
    for (int nt = 0; nt < 8; nt++)
#pragma unroll
      for (int e = 0; e < 4; e++) acc[mt][nt][e] = 0.f;

  const int lr = lane & 15, lc = lane >> 4;
  uint32_t a_base = (uint32_t)((wm * 32 + lr) * 80 + lc * 16);
  uint32_t b_base = (uint32_t)(lr * 272 + wn * 128 + lc * 16);

  auto stage = [&](int it, int slot) {
    const int c0 = it * 32;
    const uint32_t sb = smb + slot * BUF_BYTES;
#pragma unroll
    for (int r = 0; r < 2; r++) {
      int row = a_row0 + r * 64;
      uint32_t so = (uint32_t)(row * 80 + a_seg * 16);
      cp_async16(sb + OFF_AH + so, Wbh + (size_t)row * NC + c0 + a_seg * 8);
      cp_async16(sb + OFF_AL + so, Wbl + (size_t)row * NC + c0 + a_seg * 8);
    }
#pragma unroll
    for (int r = 0; r < 2; r++) {
      int row = b_row0 + r * 16;
      uint32_t so = (uint32_t)(row * 272 + b_seg * 16);
      cp_async16(sb + OFF_BH + so, Xbh + (size_t)(c0 + row) * NHW + b_seg * 8);
      cp_async16(sb + OFF_BL + so, Xbl + (size_t)(c0 + row) * NHW + b_seg * 8);
    }
    CP_COMMIT();
  };

  stage(0, 0);
  stage(1, 1);

  int slot = 0;
  for (int it = 0; it < 8; it++) {
    if (it < 7) { CP_WAIT1(); } else { CP_WAIT0(); }
    __syncthreads();
    int pslot = slot + 2 >= 3 ? slot - 1 : slot + 2;
    if (it + 2 < 8) stage(it + 2, pslot);

    const uint32_t sb = smb + slot * BUF_BYTES;
#pragma unroll
    for (int ks = 0; ks < 2; ks++) {
      uint32_t ah[2][4], al[2][4];
#pragma unroll
      for (int mt = 0; mt < 2; mt++) {
        uint32_t ao = sb + a_base + (uint32_t)(mt * 16 * 80 + ks * 32);
        ldsm_x4(ah[mt], ao + OFF_AH);
        ldsm_x4(al[mt], ao + OFF_AL);
      }
#pragma unroll
      for (int nt2 = 0; nt2 < 4; nt2++) {
        uint32_t bh[4], bl[4];
        uint32_t bo = sb + b_base + (uint32_t)(ks * 16 * 272 + nt2 * 32);
        ldsm_x4_t(bh, bo + OFF_BH);
        ldsm_x4_t(bl, bo + OFF_BL);
        mma_bf16(acc[0][nt2 * 2],     ah[0], bh[0], bh[1]);   // hi*hi
        mma_bf16(acc[0][nt2 * 2 + 1], ah[0], bh[2], bh[3]);
        mma_bf16(acc[1][nt2 * 2],     ah[1], bh[0], bh[1]);
        mma_bf16(acc[1][nt2 * 2 + 1], ah[1], bh[2], bh[3]);
        mma_bf16(acc[0][nt2 * 2],     ah[0], bl[0], bl[1]);   // hi*lo
        mma_bf16(acc[0][nt2 * 2 + 1], ah[0], bl[2], bl[3]);
        mma_bf16(acc[1][nt2 * 2],     ah[1], bl[0], bl[1]);
        mma_bf16(acc[1][nt2 * 2 + 1], ah[1], bl[2], bl[3]);
        mma_bf16(acc[0][nt2 * 2],     al[0], bh[0], bh[1]);   // lo*hi
        mma_bf16(acc[0][nt2 * 2 + 1], al[0], bh[2], bh[3]);
        mma_bf16(acc[1][nt2 * 2],     al[1], bh[0], bh[1]);
        mma_bf16(acc[1][nt2 * 2 + 1], al[1], bh[2], bh[3]);
      }
    }
    slot = slot + 1 >= 3 ? 0 : slot + 1;
  }
  __syncthreads();

#pragma unroll
  for (int mt = 0; mt < 2; mt++) {
    int o = o0 + wm * 32 + mt * 16 + (lane >> 2);
    float bv0 = __ldg(bias + o);
    float bv1 = __ldg(bias + o + 8);
#pragma unroll
    for (int nt = 0; nt < 8; nt++) {
      int n = n0 + wn * 64 + nt * 8 + (lane & 3) * 2;
      float v00 = acc[mt][nt][0] + bv0, v01 = acc[mt][nt][1] + bv0;
      float v10 = acc[mt][nt][2] + bv1, v11 = acc[mt][nt][3] + bv1;
      size_t off0 = ((size_t)b * ocnt + o) * NHW + n;
      size_t off1 = ((size_t)b * ocnt + o + 8) * NHW + n;
      if (Yf) {
        *(float2*)(Yf + off0) = make_float2(v00, v01);
        *(float2*)(Yf + off1) = make_float2(v10, v11);
      } else {
        *(uint32_t*)(Yh + off0) = pack_hi(v00, v01);
        *(uint32_t*)(Yh + off1) = pack_hi(v10, v11);
        *(uint32_t*)(Yl + off0) = pack_lo(v00, v01);
        *(uint32_t*)(Yl + off1) = pack_lo(v10, v11);
      }
    }
  }
}

// ---------------------------------------------------------------------------
// Persistent tensor-core attention (R11 best):
//   wait1(QK)/sync -> S -> wait0(V)/sync -> QK(next) prefetch ->
//   exp-only softmax (no max, unnormalized P) -> PV (barrier-free entry) ->
//   sync -> V(next) prefetch -> epilogue (normalize by 1/rowsum).
// ---------------------------------------------------------------------------
#define AT_Q 0
#define AT_K 69632
#define AT_V 139264
#define SMEM_ATTN 208896

__global__ __launch_bounds__(256) void attn_mma(
    const __nv_bfloat16* __restrict__ QKVh,
    const __nv_bfloat16* __restrict__ QKVl,
    __nv_bfloat16* __restrict__ Oh, __nv_bfloat16* __restrict__ Ol) {
  extern __shared__ __align__(16) char sm[];
  const uint32_t smb = smem_u32(sm);

  const int tid  = threadIdx.x;
  const int lane = tid & 31;
  const int wid  = tid >> 5;
  const int lr = lane & 15, lc = lane >> 4;
  const int g = lane >> 2, tig = lane & 3;
  const int r0 = wid * 16;
  const int srow = tid >> 4, sseg = tid & 15;
  const int nchan = NB * NC;

  auto stage128 = [&](uint32_t region, size_t goff) {
    const uint32_t sb = smb + region;
#pragma unroll
    for (int r = 0; r < 8; r++) {
      int row = srow + r * 16;
      uint32_t so = (uint32_t)(row * 272 + sseg * 16);
      cp_async16(sb + so,         QKVh + goff + row * 128 + sseg * 8);
      cp_async16(sb + 34816 + so, QKVl + goff + row * 128 + sseg * 8);
    }
  };
  auto qoff = [&](int q) {
    return ((size_t)(q >> 8) * 3 * NC + (q & 255)) * NHW;
  };

  const int c0 = blockIdx.x;
  stage128(AT_Q, qoff(c0));
  stage128(AT_K, qoff(c0) + (size_t)NC * NHW);
  CP_COMMIT();
  stage128(AT_V, qoff(c0) + (size_t)2 * NC * NHW);
  CP_COMMIT();

  for (int q = c0; q < nchan; q += gridDim.x) {
    const int qn = q + gridDim.x;

    CP_WAIT1();          // QK(q) done (V(q) may pend)
    __syncthreads();

    // S = Q K^T
    float acc[16][4];
#pragma unroll
    for (int j = 0; j < 16; j++)
#pragma unroll
      for (int e = 0; e < 4; e++) acc[j][e] = 0.f;

#pragma unroll
    for (int ks = 0; ks < 8; ks++) {
      uint32_t qh[4], ql[4];
      uint32_t ao = smb + AT_Q + (uint32_t)((r0 + lr) * 272 + ks * 32 + lc * 16);
      ldsm_x4(qh, ao);
      ldsm_x4(ql, ao + 34816);
#pragma unroll
      for (int nt = 0; nt < 8; nt += 2) {
        uint32_t kh0[4], kl0[4], kh1[4], kl1[4];
        uint32_t bo0 = smb + AT_K + (uint32_t)((nt * 16 + lr) * 272 + ks * 32 + lc * 16);
        uint32_t bo1 = bo0 + 16 * 272;
        ldsm_x4(kh0, bo0);
        ldsm_x4(kl0, bo0 + 34816);
        ldsm_x4(kh1, bo1);
        ldsm_x4(kl1, bo1 + 34816);
        mma_bf16(acc[2 * nt],     qh, kh0[0], kh0[2]);
        mma_bf16(acc[2 * nt + 1], qh, kh0[1], kh0[3]);
        mma_bf16(acc[2 * nt + 2], qh, kh1[0], kh1[2]);
        mma_bf16(acc[2 * nt + 3], qh, kh1[1], kh1[3]);
        mma_bf16(acc[2 * nt],     qh, kl0[0], kl0[2]);
        mma_bf16(acc[2 * nt + 1], qh, kl0[1], kl0[3]);
        mma_bf16(acc[2 * nt + 2], qh, kl1[0], kl1[2]);
        mma_bf16(acc[2 * nt + 3], qh, kl1[1], kl1[3]);
        mma_bf16(acc[2 * nt],     ql, kh0[0], kh0[2]);
        mma_bf16(acc[2 * nt + 1], ql, kh0[1], kh0[3]);
        mma_bf16(acc[2 * nt + 2], ql, kh1[0], kh1[2]);
        mma_bf16(acc[2 * nt + 3], ql, kh1[1], kh1[3]);
      }
    }

    CP_WAIT0();          // V(q) done
    __syncthreads();     // V visible + all QK readers finished

    if (qn < nchan) {    // prefetch QK(next) — overlaps softmax+PV+epilogue
      stage128(AT_Q, qoff(qn));
      stage128(AT_K, qoff(qn) + (size_t)NC * NHW);
    }
    CP_COMMIT();

    // exp-only softmax: no max-subtract; P unnormalized; 1/rowsum in epilogue
    const float C = 0.42044820762685725f * 1.4426950408889634f;
    float sA = 0.f, sB = 0.f;
#pragma unroll
    for (int j = 0; j < 16; j++) {
      acc[j][0] = ex2(acc[j][0] * C);
      acc[j][1] = ex2(acc[j][1] * C);
      acc[j][2] = ex2(acc[j][2] * C);
      acc[j][3] = ex2(acc[j][3] * C);
      sA += acc[j][0] + acc[j][1];
      sB += acc[j][2] + acc[j][3];
    }

    uint32_t ph[8][4], pl[8][4];
#pragma unroll
    for (int ky = 0; ky < 8; ky++) {
      const int j0 = 2 * ky, j1 = 2 * ky + 1;
      ph[ky][0] = pack_hi(acc[j0][0], acc[j0][1]);
      ph[ky][1] = pack_hi(acc[j0][2], acc[j0][3]);
      ph[ky][2] = pack_hi(acc[j1][0], acc[j1][1]);
      ph[ky][3] = pack_hi(acc[j1][2], acc[j1][3]);
      pl[ky][0] = pack_lo(acc[j0][0], acc[j0][1]);
      pl[ky][1] = pack_lo(acc[j0][2], acc[j0][3]);
      pl[ky][2] = pack_lo(acc[j1][0], acc[j1][1]);
      pl[ky][3] = pack_lo(acc[j1][2], acc[j1][3]);
    }

    sA += __shfl_xor_sync(0xffffffffu, sA, 1);
    sA += __shfl_xor_sync(0xffffffffu, sA, 2);
    sB += __shfl_xor_sync(0xffffffffu, sB, 1);
    sB += __shfl_xor_sync(0xffffffffu, sB, 2);
    const float rA = 1.0f / sA, rB = 1.0f / sB;

    // O = P V (barrier-free entry)
    float oac[16][4];
#pragma unroll
    for (int j = 0; j < 16; j++)
#pragma unroll
      for (int e = 0; e < 4; e++) oac[j][e] = 0.f;

#pragma unroll
    for (int ky = 0; ky < 8; ky++) {
#pragma unroll
      for (int nt = 0; nt < 8; nt += 2) {
        uint32_t vh0[4], vl0[4], vh1[4], vl1[4];
        uint32_t bo0 = smb + AT_V + (uint32_t)((ky * 16 + lr) * 272 + nt * 32 + lc * 16);
        uint32_t bo1 = bo0 + 32;
        ldsm_x4_t(vh0, bo0);
        ldsm_x4_t(vl0, bo0 + 34816);
        ldsm_x4_t(vh1, bo1);
        ldsm_x4_t(vl1, bo1 + 34816);
        mma_bf16(oac[2 * nt],     ph[ky], vh0[0], vh0[1]);
        mma_bf16(oac[2 * nt + 1], ph[ky], vh0[2], vh0[3]);
        mma_bf16(oac[2 * nt + 2], ph[ky], vh1[0], vh1[1]);
        mma_bf16(oac[2 * nt + 3], ph[ky], vh1[2], vh1[3]);
        mma_bf16(oac[2 * nt],     ph[ky], vl0[0], vl0[1]);
        mma_bf16(oac[2 * nt + 1], ph[ky], vl0[2], vl0[3]);
        mma_bf16(oac[2 * nt + 2], ph[ky], vl1[0], vl1[1]);
        mma_bf16(oac[2 * nt + 3], ph[ky], vl1[2], vl1[3]);
        mma_bf16(oac[2 * nt],     pl[ky], vh0[0], vh0[1]);
        mma_bf16(oac[2 * nt + 1], pl[ky], vh0[2], vh0[3]);
        mma_bf16(oac[2 * nt + 2], pl[ky], vh1[0], vh1[1]);
        mma_bf16(oac[2 * nt + 3], pl[ky], vh1[2], vh1[3]);
      }
    }

    __syncthreads();     // all warps done reading V
    if (qn < nchan)      // prefetch V(next) — overlaps store + next S
      stage128(AT_V, qoff(qn) + (size_t)2 * NC * NHW);
    CP_COMMIT();

    // Epilogue: normalize rows, write O hi/lo bf16 at [q][row*128+col]
    const size_t ob = (size_t)q * NHW;
    const int row0 = r0 + g, row1 = r0 + g + 8;
#pragma unroll
    for (int j = 0; j < 16; j++) {
      int col = j * 8 + tig * 2;
      float v00 = oac[j][0] * rA, v01 = oac[j][1] * rA;
      float v10 = oac[j][2] * rB, v11 = oac[j][3] * rB;
      size_t o0 = ob + (size_t)row0 * 128 + col;
      size_t o1 = ob + (size_t)row1 * 128 + col;
      *(uint32_t*)(Oh + o0) = pack_hi(v00, v01);
      *(uint32_t*)(Oh + o1) = pack_hi(v10, v11);
      *(uint32_t*)(Ol + o0) = pack_lo(v00, v01);
      *(uint32_t*)(Ol + o1) = pack_lo(v10, v11);
    }
  }
}

// ---------------------------------------------------------------------------
extern "C" void kernel_launch(void* const* d_in, const int* in_sizes, int n_in,
                              void* d_out, int out_size) {
  const float* x  = (const float*)d_in[0];
  const float* wq = (const float*)d_in[1];
  const float* bq = (const float*)d_in[2];
  const float* wk = (const float*)d_in[3];
  const float* bk = (const float*)d_in[4];
  const float* wv = (const float*)d_in[5];
  const float* bv = (const float*)d_in[6];
  const float* wo = (const float*)d_in[7];
  const float* bo = (const float*)d_in[8];

  __nv_bfloat16 *xh, *xl, *qkvh, *qkvl, *ath, *atl, *wh, *wl;
  float* bias;
  cudaGetSymbolAddress((void**)&xh,   g_x_hi);
  cudaGetSymbolAddress((void**)&xl,   g_x_lo);
  cudaGetSymbolAddress((void**)&qkvh, g_qkv_hi);
  cudaGetSymbolAddress((void**)&qkvl, g_qkv_lo);
  cudaGetSymbolAddress((void**)&ath,  g_att_hi);
  cudaGetSymbolAddress((void**)&atl,  g_att_lo);
  cudaGetSymbolAddress((void**)&wh,   g_w_hi);
  cudaGetSymbolAddress((void**)&wl,   g_w_lo);
  cudaGetSymbolAddress((void**)&bias, g_bias);

  int nsm = 148;
  cudaDeviceGetAttribute(&nsm, cudaDevAttrMultiProcessorCount, 0);
  if (nsm > NB * NC) nsm = NB * NC;

  cudaFuncSetAttribute(gemm_mma,
                       cudaFuncAttributeMaxDynamicSharedMemorySize, SMEM_GEMM);
  cudaFuncSetAttribute(attn_mma,
                       cudaFuncAttributeMaxDynamicSharedMemorySize, SMEM_ATTN);

  // Convert inputs
  split_f32<<<NB * NC * NHW / 4 / 256, 256>>>(x, xh, xl);
  convert_w<<<dim3(NC * NC / 256, 4), 256>>>(wq, wk, wv, wo, bq, bk, bv, bo, wh, wl);

  // Fused QKV projection -> bf16 hi/lo
  gemm_mma<<<dim3(6, NHW / 128, NB), 256, SMEM_GEMM>>>(
      xh, xl, wh, wl, bias, nullptr, qkvh, qkvl, 3 * NC);

  // Persistent tensor-core attention -> bf16 hi/lo
  attn_mma<<<nsm, 256, SMEM_ATTN>>>(qkvh, qkvl, ath, atl);

  // Output projection -> fp32 d_out
  gemm_mma<<<dim3(2, NHW / 128, NB), 256, SMEM_GEMM>>>(
      ath, atl, wh + 3 * NC * NC, wl + 3 * NC * NC, bias + 3 * NC,
      (float*)d_out, nullptr, nullptr, NC);
}